// round 3
// baseline (speedup 1.0000x reference)
#include <cuda_runtime.h>

#define H 512
#define W 512
#define NB 32
#define OUTW 56            // output columns per warp (lanes 0..27 x 2)
#define STRIPS 10          // 10*56 = 560 >= 512
#define YSEGS 8
#define YLEN 64
#define WARPS_TOTAL (STRIPS * NB * YSEGS)   // 2560
#define NBLOCKS (WARPS_TOTAL / 4)           // 640

__device__ float g_part[NBLOCKS];
__device__ int   g_cnt = 0;

// Pair-channel horizontal 9-window sums. Lane l holds columns 2l (a0), 2l+1 (a1).
// hE[l] = sum cols 2l..2l+8, hO[l] = sum cols 2l+1..2l+9. Valid for l <= 27.
#define HSUM9P(a0, a1, hE, hO) do {                          \
    float _p  = (a0) + (a1);                                 \
    float _s  = _p + __shfl_down_sync(0xffffffffu, _p, 1);   \
    float _S4 = _s + __shfl_down_sync(0xffffffffu, _s, 2);   \
    (hE) = _S4  + __shfl_down_sync(0xffffffffu, (a0), 4);    \
    (hO) = (a1) + __shfl_down_sync(0xffffffffu, _S4, 1);     \
} while (0)

__global__ __launch_bounds__(128, 4) void cc_kernel(const float* __restrict__ inp,
                                                    const float* __restrict__ tgt,
                                                    float* __restrict__ out) {
    const int lane = threadIdx.x & 31;
    const int wid  = threadIdx.x >> 5;
    const int w    = blockIdx.x * 4 + wid;

    const int strip = w % STRIPS;
    const int rem   = w / STRIPS;          // 0..255
    const int b     = rem >> 3;            // 0..31
    const int y0    = (rem & 7) * YLEN;    // 0..448

    const int xs  = strip * OUTW;
    const int gx  = xs - 4 + 2 * lane;     // even, first of this lane's pair
    const bool cok = (unsigned)gx < W;     // gx>=0 && gx+1<512 (gx even)

    const int ocolE = xs + 2 * lane;
    const bool valE = (lane < 28) && (ocolE     < W);
    const bool valO = (lane < 28) && (ocolE + 1 < W);

    const size_t boff = (size_t)b * (H * W) + (cok ? gx : 0);
    const float2* __restrict__ pI2 = (const float2*)(inp + boff);
    const float2* __restrict__ pT2 = (const float2*)(tgt + boff);

    // vertical ring buffers: 5 channels x 2 columns x 9 rows
    float rAE[9], rAO[9], rBE[9], rBO[9], rAAE[9], rAAO[9],
          rBBE[9], rBBO[9], rABE[9], rABO[9];
    #pragma unroll
    for (int k = 0; k < 9; k++) {
        rAE[k]=0.f; rAO[k]=0.f; rBE[k]=0.f; rBO[k]=0.f; rAAE[k]=0.f;
        rAAO[k]=0.f; rBBE[k]=0.f; rBBO[k]=0.f; rABE[k]=0.f; rABO[k]=0.f;
    }
    float SAE=0.f, SAO=0.f, SBE=0.f, SBO=0.f, SAAE=0.f, SAAO=0.f,
          SBBE=0.f, SBBO=0.f, SABE=0.f, SABO=0.f, acc=0.f;

    const float inv81 = 1.0f / 81.0f;

    #pragma unroll 1
    for (int j = 0; j < 8; j++) {
        #pragma unroll
        for (int k = 0; k < 9; k++) {
            const int i  = j * 9 + k;            // 0..71
            const int gy = y0 - 4 + i;
            const bool ok = cok && ((unsigned)gy < H);
            float iv0 = 0.f, iv1 = 0.f, tv0 = 0.f, tv1 = 0.f;
            if (ok) {
                const float2 I2 = __ldg(pI2 + (size_t)gy * (W / 2));
                const float2 T2 = __ldg(pT2 + (size_t)gy * (W / 2));
                iv0 = I2.x; iv1 = I2.y;
                tv0 = fmaf(T2.x, 0.5f, 0.5f);    // rescale to [0,1]; pad stays 0
                tv1 = fmaf(T2.y, 0.5f, 0.5f);
            }
            const float ii0 = iv0 * iv0, ii1 = iv1 * iv1;
            const float tt0 = tv0 * tv0, tt1 = tv1 * tv1;
            const float it0 = iv0 * tv0, it1 = iv1 * tv1;

            float hAE, hAO, hBE, hBO, hAAE, hAAO, hBBE, hBBO, hABE, hABO;
            HSUM9P(iv0, iv1, hAE,  hAO);
            HSUM9P(tv0, tv1, hBE,  hBO);
            HSUM9P(ii0, ii1, hAAE, hAAO);
            HSUM9P(tt0, tt1, hBBE, hBBO);
            HSUM9P(it0, it1, hABE, hABO);

            SAE  += hAE  - rAE [k];  rAE [k] = hAE;
            SAO  += hAO  - rAO [k];  rAO [k] = hAO;
            SBE  += hBE  - rBE [k];  rBE [k] = hBE;
            SBO  += hBO  - rBO [k];  rBO [k] = hBO;
            SAAE += hAAE - rAAE[k];  rAAE[k] = hAAE;
            SAAO += hAAO - rAAO[k];  rAAO[k] = hAAO;
            SBBE += hBBE - rBBE[k];  rBBE[k] = hBBE;
            SBBO += hBBO - rBBO[k];  rBBO[k] = hBBO;
            SABE += hABE - rABE[k];  rABE[k] = hABE;
            SABO += hABO - rABO[k];  rABO[k] = hABO;

            if (i >= 8) {
                {
                    const float tA = SAE * inv81, tB = SBE * inv81;
                    const float cross = fmaf(-tA, SBE, SABE);
                    const float ivar  = fmaf(-tA, SAE, SAAE);
                    const float tvar  = fmaf(-tB, SBE, SBBE);
                    const float cc = __fdividef(cross * cross, fmaf(tvar, ivar, 1e-5f));
                    acc += valE ? cc : 0.f;
                }
                {
                    const float tA = SAO * inv81, tB = SBO * inv81;
                    const float cross = fmaf(-tA, SBO, SABO);
                    const float ivar  = fmaf(-tA, SAO, SAAO);
                    const float tvar  = fmaf(-tB, SBO, SBBO);
                    const float cc = __fdividef(cross * cross, fmaf(tvar, ivar, 1e-5f));
                    acc += valO ? cc : 0.f;
                }
            }
        }
    }

    // ---- reduction: warp -> block -> global partials -> last block finishes ----
    #pragma unroll
    for (int off = 16; off > 0; off >>= 1)
        acc += __shfl_down_sync(0xffffffffu, acc, off);

    __shared__ float sred[4];
    __shared__ int   slast;
    if (lane == 0) sred[wid] = acc;
    __syncthreads();
    if (threadIdx.x == 0) {
        g_part[blockIdx.x] = sred[0] + sred[1] + sred[2] + sred[3];
        __threadfence();
        int old = atomicAdd(&g_cnt, 1);
        slast = (old == NBLOCKS - 1) ? 1 : 0;
    }
    __syncthreads();

    if (slast) {
        double d = 0.0;
        for (int idx = threadIdx.x; idx < NBLOCKS; idx += 128)
            d += (double)__ldcg(&g_part[idx]);
        #pragma unroll
        for (int off = 16; off > 0; off >>= 1)
            d += __shfl_down_sync(0xffffffffu, d, off);
        __shared__ double dred[4];
        if (lane == 0) dred[wid] = d;
        __syncthreads();
        if (threadIdx.x == 0) {
            double tot = dred[0] + dred[1] + dred[2] + dred[3];
            out[0] = (float)(-tot / 8388608.0);   // 32*512*512
            g_cnt = 0;                            // reset for next graph replay
        }
    }
}

extern "C" void kernel_launch(void* const* d_in, const int* in_sizes, int n_in,
                              void* d_out, int out_size) {
    const float* inp = (const float*)d_in[0];
    const float* tgt = (const float*)d_in[1];
    // d_in[2] is the all-ones 9x9 filter; baked into the box sums.
    float* out = (float*)d_out;
    cc_kernel<<<NBLOCKS, 128>>>(inp, tgt, out);
}

// round 4
// speedup vs baseline: 1.6676x; 1.6676x over previous
#include <cuda_runtime.h>

#define H 512
#define W 512
#define NB 32
#define OUTW 56            // output columns per warp (lanes 0..27 x 2)
#define STRIPS 10          // 10*56 = 560 >= 512
#define YSEGS 8
#define YLEN 64
#define WARPS_TOTAL (STRIPS * NB * YSEGS)   // 2560
#define NBLOCKS (WARPS_TOTAL / 4)           // 640

__device__ float g_part[NBLOCKS];
__device__ int   g_cnt = 0;

// Pair-channel horizontal 9-window sums. Lane l holds columns 2l (a0), 2l+1 (a1).
// hE[l] = sum cols 2l..2l+8, hO[l] = sum cols 2l+1..2l+9. Valid for l <= 27.
#define HSUM9P(a0, a1, hE, hO) do {                          \
    float _p  = (a0) + (a1);                                 \
    float _s  = _p + __shfl_down_sync(0xffffffffu, _p, 1);   \
    float _S4 = _s + __shfl_down_sync(0xffffffffu, _s, 2);   \
    (hE) = _S4  + __shfl_down_sync(0xffffffffu, (a0), 4);    \
    (hO) = (a1) + __shfl_down_sync(0xffffffffu, _S4, 1);     \
} while (0)

__global__ __launch_bounds__(128, 5) void cc_kernel(const float* __restrict__ inp,
                                                    const float* __restrict__ tgt,
                                                    float* __restrict__ out) {
    const int lane = threadIdx.x & 31;
    const int wid  = threadIdx.x >> 5;
    const int w    = blockIdx.x * 4 + wid;

    const int strip = w % STRIPS;
    const int rem   = w / STRIPS;          // 0..255
    const int b     = rem >> 3;            // 0..31
    const int y0    = (rem & 7) * YLEN;    // 0..448

    const int xs  = strip * OUTW;
    const int gx  = xs - 4 + 2 * lane;     // even, first of this lane's pair
    const bool cok = (unsigned)gx < W;

    const int ocolE = xs + 2 * lane;
    const bool valE = (lane < 28) && (ocolE     < W);
    const bool valO = (lane < 28) && (ocolE + 1 < W);

    const size_t boff = (size_t)b * (H * W) + (cok ? gx : 0);
    const float2* __restrict__ pI2 = (const float2*)(inp + boff);
    const float2* __restrict__ pT2 = (const float2*)(tgt + boff);

    // vertical ring buffers of RAW rows: 4 values x 9 rows = 36 regs
    float ri0[9], ri1[9], rt0[9], rt1[9];
    #pragma unroll
    for (int k = 0; k < 9; k++) { ri0[k]=0.f; ri1[k]=0.f; rt0[k]=0.f; rt1[k]=0.f; }

    // vertical running sums per column: 5 channels x 2 cols
    float VA0=0.f, VA1=0.f, VB0=0.f, VB1=0.f, VAA0=0.f, VAA1=0.f,
          VBB0=0.f, VBB1=0.f, VAB0=0.f, VAB1=0.f, acc=0.f;

    const float inv81 = 1.0f / 81.0f;

    // prefetch first row (gy = y0-4)
    float2 cI = make_float2(0.f, 0.f), cT = make_float2(0.f, 0.f);
    {
        const int gy = y0 - 4;
        if (cok && (unsigned)gy < H) {
            cI = __ldg(pI2 + (size_t)gy * (W / 2));
            const float2 t = __ldg(pT2 + (size_t)gy * (W / 2));
            cT.x = fmaf(t.x, 0.5f, 0.5f);
            cT.y = fmaf(t.y, 0.5f, 0.5f);
        }
    }

    #pragma unroll 1
    for (int j = 0; j < 8; j++) {
        #pragma unroll
        for (int k = 0; k < 9; k++) {
            const int i  = j * 9 + k;            // 0..71
            const int gy = y0 - 4 + i;

            // prefetch next row
            float2 nI = make_float2(0.f, 0.f), nT = make_float2(0.f, 0.f);
            if (cok && (unsigned)(gy + 1) < H && i < 71) {
                nI = __ldg(pI2 + (size_t)(gy + 1) * (W / 2));
                const float2 t = __ldg(pT2 + (size_t)(gy + 1) * (W / 2));
                nT.x = fmaf(t.x, 0.5f, 0.5f);
                nT.y = fmaf(t.y, 0.5f, 0.5f);
            }

            const float iv0 = cI.x, iv1 = cI.y, tv0 = cT.x, tv1 = cT.y;
            const float oi0 = ri0[k], oi1 = ri1[k], ot0 = rt0[k], ot1 = rt1[k];

            // vertical running-sum updates (enter new row, exit old row)
            VA0 += iv0 - oi0;                    VA1 += iv1 - oi1;
            VB0 += tv0 - ot0;                    VB1 += tv1 - ot1;
            VAA0 = fmaf(-oi0, oi0, fmaf(iv0, iv0, VAA0));
            VAA1 = fmaf(-oi1, oi1, fmaf(iv1, iv1, VAA1));
            VBB0 = fmaf(-ot0, ot0, fmaf(tv0, tv0, VBB0));
            VBB1 = fmaf(-ot1, ot1, fmaf(tv1, tv1, VBB1));
            VAB0 = fmaf(-oi0, ot0, fmaf(iv0, tv0, VAB0));
            VAB1 = fmaf(-oi1, ot1, fmaf(iv1, tv1, VAB1));

            ri0[k] = iv0; ri1[k] = iv1; rt0[k] = tv0; rt1[k] = tv1;

            if (i >= 8) {
                // horizontal 9-sums of the vertical sums -> full 9x9 box sums
                float SAE, SAO, SBE, SBO, SAAE, SAAO, SBBE, SBBO, SABE, SABO;
                HSUM9P(VA0,  VA1,  SAE,  SAO);
                HSUM9P(VB0,  VB1,  SBE,  SBO);
                HSUM9P(VAA0, VAA1, SAAE, SAAO);
                HSUM9P(VBB0, VBB1, SBBE, SBBO);
                HSUM9P(VAB0, VAB1, SABE, SABO);
                {
                    const float tA = SAE * inv81, tB = SBE * inv81;
                    const float cross = fmaf(-tA, SBE, SABE);
                    const float ivar  = fmaf(-tA, SAE, SAAE);
                    const float tvar  = fmaf(-tB, SBE, SBBE);
                    const float cc = __fdividef(cross * cross, fmaf(tvar, ivar, 1e-5f));
                    acc += valE ? cc : 0.f;
                }
                {
                    const float tA = SAO * inv81, tB = SBO * inv81;
                    const float cross = fmaf(-tA, SBO, SABO);
                    const float ivar  = fmaf(-tA, SAO, SAAO);
                    const float tvar  = fmaf(-tB, SBO, SBBO);
                    const float cc = __fdividef(cross * cross, fmaf(tvar, ivar, 1e-5f));
                    acc += valO ? cc : 0.f;
                }
            }

            cI = nI; cT = nT;
        }
    }

    // ---- reduction: warp -> block -> global partials -> last block finishes ----
    #pragma unroll
    for (int off = 16; off > 0; off >>= 1)
        acc += __shfl_down_sync(0xffffffffu, acc, off);

    __shared__ float sred[4];
    __shared__ int   slast;
    if (lane == 0) sred[wid] = acc;
    __syncthreads();
    if (threadIdx.x == 0) {
        g_part[blockIdx.x] = sred[0] + sred[1] + sred[2] + sred[3];
        __threadfence();
        int old = atomicAdd(&g_cnt, 1);
        slast = (old == NBLOCKS - 1) ? 1 : 0;
    }
    __syncthreads();

    if (slast) {
        double d = 0.0;
        for (int idx = threadIdx.x; idx < NBLOCKS; idx += 128)
            d += (double)__ldcg(&g_part[idx]);
        #pragma unroll
        for (int off = 16; off > 0; off >>= 1)
            d += __shfl_down_sync(0xffffffffu, d, off);
        __shared__ double dred[4];
        if (lane == 0) dred[wid] = d;
        __syncthreads();
        if (threadIdx.x == 0) {
            double tot = dred[0] + dred[1] + dred[2] + dred[3];
            out[0] = (float)(-tot / 8388608.0);   // 32*512*512
            g_cnt = 0;                            // reset for next graph replay
        }
    }
}

extern "C" void kernel_launch(void* const* d_in, const int* in_sizes, int n_in,
                              void* d_out, int out_size) {
    const float* inp = (const float*)d_in[0];
    const float* tgt = (const float*)d_in[1];
    // d_in[2] is the all-ones 9x9 filter; baked into the box sums.
    float* out = (float*)d_out;
    cc_kernel<<<NBLOCKS, 128>>>(inp, tgt, out);
}

// round 5
// speedup vs baseline: 1.7717x; 1.0624x over previous
#include <cuda_runtime.h>

#define H 512
#define W 512
#define NB 32
#define OUTW 56            // output columns per warp (lanes 0..27 x 2)
#define STRIPS 10          // 10*56 = 560 >= 512
#define YSEGS 8
#define YLEN 64
#define WARPS_TOTAL (STRIPS * NB * YSEGS)   // 2560
#define WPB 2                                // warps per block
#define NBLOCKS (WARPS_TOTAL / WPB)          // 1280

__device__ float g_part[NBLOCKS];
__device__ int   g_cnt = 0;

// Pair-channel horizontal 9-window sums. Lane l holds columns 2l (a0), 2l+1 (a1).
// hE[l] = sum cols 2l..2l+8, hO[l] = sum cols 2l+1..2l+9. Valid for l <= 27.
#define HSUM9P(a0, a1, hE, hO) do {                          \
    float _p  = (a0) + (a1);                                 \
    float _s  = _p + __shfl_down_sync(0xffffffffu, _p, 1);   \
    float _S4 = _s + __shfl_down_sync(0xffffffffu, _s, 2);   \
    (hE) = _S4  + __shfl_down_sync(0xffffffffu, (a0), 4);    \
    (hO) = (a1) + __shfl_down_sync(0xffffffffu, _S4, 1);     \
} while (0)

__global__ __launch_bounds__(64, 10) void cc_kernel(const float* __restrict__ inp,
                                                    const float* __restrict__ tgt,
                                                    float* __restrict__ out) {
    const int lane = threadIdx.x & 31;
    const int wid  = threadIdx.x >> 5;
    const int w    = blockIdx.x * WPB + wid;

    const int strip = w % STRIPS;
    const int rem   = w / STRIPS;          // 0..255
    const int b     = rem >> 3;            // 0..31
    const int y0    = (rem & 7) * YLEN;    // 0..448

    const int xs  = strip * OUTW;
    const int gx  = xs - 4 + 2 * lane;     // even, first of this lane's pair
    const bool cok = (unsigned)gx < W;

    const int ocolE = xs + 2 * lane;
    const bool valE = (lane < 28) && (ocolE     < W);
    const bool valO = (lane < 28) && (ocolE + 1 < W);

    const size_t boff = (size_t)b * (H * W) + (cok ? gx : 0);
    const float2* __restrict__ pI2 = (const float2*)(inp + boff);
    const float2* __restrict__ pT2 = (const float2*)(tgt + boff);

    // vertical ring buffers of RAW rows: 4 values x 9 rows = 36 regs
    float ri0[9], ri1[9], rt0[9], rt1[9];
    #pragma unroll
    for (int k = 0; k < 9; k++) { ri0[k]=0.f; ri1[k]=0.f; rt0[k]=0.f; rt1[k]=0.f; }

    // vertical running sums per column: 5 channels x 2 cols
    float VA0=0.f, VA1=0.f, VB0=0.f, VB1=0.f, VAA0=0.f, VAA1=0.f,
          VBB0=0.f, VBB1=0.f, VAB0=0.f, VAB1=0.f, acc=0.f;

    const float inv81 = 1.0f / 81.0f;

    // prefetch first row (gy = y0-4)
    float2 cI = make_float2(0.f, 0.f), cT = make_float2(0.f, 0.f);
    {
        const int gy = y0 - 4;
        if (cok && (unsigned)gy < H) {
            cI = __ldg(pI2 + (size_t)gy * (W / 2));
            const float2 t = __ldg(pT2 + (size_t)gy * (W / 2));
            cT.x = fmaf(t.x, 0.5f, 0.5f);
            cT.y = fmaf(t.y, 0.5f, 0.5f);
        }
    }

    #pragma unroll 1
    for (int j = 0; j < 8; j++) {
        #pragma unroll
        for (int k = 0; k < 9; k++) {
            const int i  = j * 9 + k;            // 0..71
            const int gy = y0 - 4 + i;

            // prefetch next row
            float2 nI = make_float2(0.f, 0.f), nT = make_float2(0.f, 0.f);
            if (cok && (unsigned)(gy + 1) < H && i < 71) {
                nI = __ldg(pI2 + (size_t)(gy + 1) * (W / 2));
                const float2 t = __ldg(pT2 + (size_t)(gy + 1) * (W / 2));
                nT.x = fmaf(t.x, 0.5f, 0.5f);
                nT.y = fmaf(t.y, 0.5f, 0.5f);
            }

            const float iv0 = cI.x, iv1 = cI.y, tv0 = cT.x, tv1 = cT.y;
            const float oi0 = ri0[k], oi1 = ri1[k], ot0 = rt0[k], ot1 = rt1[k];

            // vertical running-sum updates (enter new row, exit old row)
            VA0 += iv0 - oi0;                    VA1 += iv1 - oi1;
            VB0 += tv0 - ot0;                    VB1 += tv1 - ot1;
            VAA0 = fmaf(-oi0, oi0, fmaf(iv0, iv0, VAA0));
            VAA1 = fmaf(-oi1, oi1, fmaf(iv1, iv1, VAA1));
            VBB0 = fmaf(-ot0, ot0, fmaf(tv0, tv0, VBB0));
            VBB1 = fmaf(-ot1, ot1, fmaf(tv1, tv1, VBB1));
            VAB0 = fmaf(-oi0, ot0, fmaf(iv0, tv0, VAB0));
            VAB1 = fmaf(-oi1, ot1, fmaf(iv1, tv1, VAB1));

            ri0[k] = iv0; ri1[k] = iv1; rt0[k] = tv0; rt1[k] = tv1;

            if (i >= 8) {
                // horizontal 9-sums of the vertical sums -> full 9x9 box sums
                float SAE, SAO, SBE, SBO, SAAE, SAAO, SBBE, SBBO, SABE, SABO;
                HSUM9P(VA0,  VA1,  SAE,  SAO);
                HSUM9P(VB0,  VB1,  SBE,  SBO);
                HSUM9P(VAA0, VAA1, SAAE, SAAO);
                HSUM9P(VBB0, VBB1, SBBE, SBBO);
                HSUM9P(VAB0, VAB1, SABE, SABO);
                {
                    const float tA = SAE * inv81, tB = SBE * inv81;
                    const float cross = fmaf(-tA, SBE, SABE);
                    const float ivar  = fmaf(-tA, SAE, SAAE);
                    const float tvar  = fmaf(-tB, SBE, SBBE);
                    const float cc = __fdividef(cross * cross, fmaf(tvar, ivar, 1e-5f));
                    acc += valE ? cc : 0.f;
                }
                {
                    const float tA = SAO * inv81, tB = SBO * inv81;
                    const float cross = fmaf(-tA, SBO, SABO);
                    const float ivar  = fmaf(-tA, SAO, SAAO);
                    const float tvar  = fmaf(-tB, SBO, SBBO);
                    const float cc = __fdividef(cross * cross, fmaf(tvar, ivar, 1e-5f));
                    acc += valO ? cc : 0.f;
                }
            }

            cI = nI; cT = nT;
        }
    }

    // ---- reduction: warp -> block -> global partials -> last block finishes ----
    #pragma unroll
    for (int off = 16; off > 0; off >>= 1)
        acc += __shfl_down_sync(0xffffffffu, acc, off);

    __shared__ float sred[WPB];
    __shared__ int   slast;
    if (lane == 0) sred[wid] = acc;
    __syncthreads();
    if (threadIdx.x == 0) {
        g_part[blockIdx.x] = sred[0] + sred[1];
        __threadfence();
        int old = atomicAdd(&g_cnt, 1);
        slast = (old == NBLOCKS - 1) ? 1 : 0;
    }
    __syncthreads();

    if (slast) {
        // 1280 partials = 320 float4; 64 threads -> 5 float4 each (high MLP)
        double d = 0.0;
        const float4* p4 = (const float4*)g_part;
        #pragma unroll
        for (int r = 0; r < 5; r++) {
            const float4 v = p4[threadIdx.x + r * 64];
            d += (double)v.x + (double)v.y + (double)v.z + (double)v.w;
        }
        #pragma unroll
        for (int off = 16; off > 0; off >>= 1)
            d += __shfl_down_sync(0xffffffffu, d, off);
        __shared__ double dred[WPB];
        if (lane == 0) dred[wid] = d;
        __syncthreads();
        if (threadIdx.x == 0) {
            out[0] = (float)(-(dred[0] + dred[1]) / 8388608.0);   // 32*512*512
            g_cnt = 0;                            // reset for next graph replay
        }
    }
}

extern "C" void kernel_launch(void* const* d_in, const int* in_sizes, int n_in,
                              void* d_out, int out_size) {
    const float* inp = (const float*)d_in[0];
    const float* tgt = (const float*)d_in[1];
    // d_in[2] is the all-ones 9x9 filter; baked into the box sums.
    float* out = (float*)d_out;
    cc_kernel<<<NBLOCKS, 64>>>(inp, tgt, out);
}